// round 1
// baseline (speedup 1.0000x reference)
#include <cuda_runtime.h>
#include <math.h>

// Problem constants
#define T_TOKENS 2048
#define HIDDEN   2048
#define INTER    5632
#define NEXP     8
#define TOPK     2
#define NPAIRS   (T_TOKENS * TOPK)   // 4096
#define CAP      2048                // max pairs per expert (each token picks an expert at most once)

// ---------------- device scratch (static: no runtime allocation) ----------------
__device__ int d_cnt[NEXP];
__device__ int d_list[NEXP * CAP];
__device__ int d_eid[NPAIRS];
__device__ float d_wgt[NPAIRS];

__device__ __align__(16) float d_G[(size_t)NPAIRS * INTER];   // gate, then act (in-place)
__device__ __align__(16) float d_U[(size_t)NPAIRS * INTER];   // up
__device__ __align__(16) float d_Y[(size_t)NPAIRS * HIDDEN];  // per-pair down-proj output

// ---------------- small kernels ----------------
__global__ void init_kernel() {
    if (threadIdx.x < NEXP) d_cnt[threadIdx.x] = 0;
}

// one warp per token: logits over 8 experts, top-2, softmax over the two
__global__ void router_kernel(const float* __restrict__ x, const float* __restrict__ wr) {
    int warp = threadIdx.x >> 5;
    int lane = threadIdx.x & 31;
    int t = blockIdx.x * 8 + warp;
    if (t >= T_TOKENS) return;

    float acc[NEXP];
#pragma unroll
    for (int e = 0; e < NEXP; e++) acc[e] = 0.f;

    const float* xr = x + (size_t)t * HIDDEN;
    for (int j = lane; j < HIDDEN; j += 32) {
        float xv = xr[j];
#pragma unroll
        for (int e = 0; e < NEXP; e++) acc[e] += xv * wr[e * HIDDEN + j];
    }
#pragma unroll
    for (int e = 0; e < NEXP; e++) {
#pragma unroll
        for (int off = 16; off; off >>= 1)
            acc[e] += __shfl_xor_sync(0xffffffffu, acc[e], off);
    }
    if (lane == 0) {
        int e0 = 0;
#pragma unroll
        for (int e = 1; e < NEXP; e++) if (acc[e] > acc[e0]) e0 = e;
        int e1 = -1;
#pragma unroll
        for (int e = 0; e < NEXP; e++) {
            if (e == e0) continue;
            if (e1 < 0 || acc[e] > acc[e1]) e1 = e;
        }
        float v0 = acc[e0], v1 = acc[e1];
        // softmax over [v0, v1], v0 >= v1
        float w1 = 1.f / (1.f + expf(v0 - v1));
        float w0 = 1.f - w1;
        d_eid[2 * t]     = e0;
        d_eid[2 * t + 1] = e1;
        d_wgt[2 * t]     = w0;
        d_wgt[2 * t + 1] = w1;
    }
}

__global__ void compact_kernel() {
    int p = blockIdx.x * blockDim.x + threadIdx.x;
    if (p >= NPAIRS) return;
    int e = d_eid[p];
    int pos = atomicAdd(&d_cnt[e], 1);
    d_list[e * CAP + pos] = p;
}

// ---------------- f32x2 helpers (Blackwell packed fp32 FMA) ----------------
__device__ __forceinline__ unsigned long long dupf2(float a) {
    unsigned long long r;
    asm("mov.b64 %0, {%1, %1};" : "=l"(r) : "f"(a));
    return r;
}
__device__ __forceinline__ void ffma2(unsigned long long& d, unsigned long long a, unsigned long long b) {
    asm("fma.rn.f32x2 %0, %1, %2, %0;" : "+l"(d) : "l"(a), "l"(b));
}
__device__ __forceinline__ float2 unpk(unsigned long long v) {
    float2 r;
    asm("mov.b64 {%0, %1}, %2;" : "=f"(r.x), "=f"(r.y) : "l"(v));
    return r;
}

// ---------------- expert-grouped SGEMM ----------------
// C[pid][n] = sum_k A[pid>>shift][k] * B_e[n][k]
// A rows gathered via per-expert pair list. B_e = Ball + e*N*K (row-major [N][K]).
// asel: 0 -> A = Aext (x), 1 -> A = d_G (act).   csel: 0 -> d_G, 1 -> d_U, 2 -> d_Y.
#define BM 128
#define BN 128
#define BK 16

__global__ __launch_bounds__(256, 2)
void gemm_expert(const float* __restrict__ Aext, const float* __restrict__ Ball,
                 int N, int K, int lda, int shift, int asel, int csel)
{
    int e = blockIdx.z;
    int n_e = d_cnt[e];
    int mbase = blockIdx.y * BM;
    if (mbase >= n_e) return;
    int nbase = blockIdx.x * BN;

    const float* A = (asel == 0) ? Aext : d_G;
    float* C = (csel == 0) ? d_G : (csel == 1) ? d_U : d_Y;
    const float* B = Ball + (size_t)e * N * K;

    __shared__ float sA[2][BK][BM];
    __shared__ float sB[2][BK][BN];
    __shared__ int s_pid[BM];

    int tid = threadIdx.x;
    if (tid < BM) {
        int lp = mbase + tid;
        s_pid[tid] = d_list[e * CAP + ((lp < n_e) ? lp : mbase)];
    }
    __syncthreads();

    // loader mapping: 2 threads per row, 8 cols each
    int lrow  = tid >> 1;
    int lhalf = (tid & 1) * 8;
    const float* aPtr = A + (size_t)(s_pid[lrow] >> shift) * lda + lhalf;
    const float* bPtr = B + (size_t)(nbase + lrow) * K + lhalf;

    int tx = tid & 15;   // n group: n0 = tx*8
    int ty = tid >> 4;   // m group: m0 = ty*8

    unsigned long long acc[8][4];
#pragma unroll
    for (int i = 0; i < 8; i++)
#pragma unroll
        for (int j = 0; j < 4; j++) acc[i][j] = 0ull;

    int KT = K / BK;

    float4 ra0, ra1, rb0, rb1;
    ra0 = *(const float4*)(aPtr);
    ra1 = *(const float4*)(aPtr + 4);
    rb0 = *(const float4*)(bPtr);
    rb1 = *(const float4*)(bPtr + 4);
#pragma unroll
    for (int j = 0; j < 4; j++) {
        sA[0][lhalf + j][lrow]     = ((float*)&ra0)[j];
        sA[0][lhalf + 4 + j][lrow] = ((float*)&ra1)[j];
        sB[0][lhalf + j][lrow]     = ((float*)&rb0)[j];
        sB[0][lhalf + 4 + j][lrow] = ((float*)&rb1)[j];
    }
    __syncthreads();

    for (int kb = 0; kb < KT; kb++) {
        int cur = kb & 1;
        if (kb + 1 < KT) {
            const float* ap = aPtr + (size_t)(kb + 1) * BK;
            const float* bp = bPtr + (size_t)(kb + 1) * BK;
            ra0 = *(const float4*)(ap);
            ra1 = *(const float4*)(ap + 4);
            rb0 = *(const float4*)(bp);
            rb1 = *(const float4*)(bp + 4);
        }
#pragma unroll
        for (int k = 0; k < BK; k++) {
            float4 af0 = *(const float4*)&sA[cur][k][ty * 8];
            float4 af1 = *(const float4*)&sA[cur][k][ty * 8 + 4];
            ulonglong2 bf0 = *(const ulonglong2*)&sB[cur][k][tx * 8];
            ulonglong2 bf1 = *(const ulonglong2*)&sB[cur][k][tx * 8 + 4];
            unsigned long long ad[8];
            ad[0] = dupf2(af0.x); ad[1] = dupf2(af0.y); ad[2] = dupf2(af0.z); ad[3] = dupf2(af0.w);
            ad[4] = dupf2(af1.x); ad[5] = dupf2(af1.y); ad[6] = dupf2(af1.z); ad[7] = dupf2(af1.w);
            unsigned long long bb[4] = { bf0.x, bf0.y, bf1.x, bf1.y };
#pragma unroll
            for (int i = 0; i < 8; i++)
#pragma unroll
                for (int j = 0; j < 4; j++)
                    ffma2(acc[i][j], ad[i], bb[j]);
        }
        if (kb + 1 < KT) {
            int nxt = cur ^ 1;
#pragma unroll
            for (int j = 0; j < 4; j++) {
                sA[nxt][lhalf + j][lrow]     = ((float*)&ra0)[j];
                sA[nxt][lhalf + 4 + j][lrow] = ((float*)&ra1)[j];
                sB[nxt][lhalf + j][lrow]     = ((float*)&rb0)[j];
                sB[nxt][lhalf + 4 + j][lrow] = ((float*)&rb1)[j];
            }
            __syncthreads();
        }
    }

#pragma unroll
    for (int i = 0; i < 8; i++) {
        int mi = ty * 8 + i;
        if (mbase + mi < n_e) {
            int pid = s_pid[mi];
            float* cp = C + (size_t)pid * N + nbase + tx * 8;
            float2 r0 = unpk(acc[i][0]), r1 = unpk(acc[i][1]);
            float2 r2 = unpk(acc[i][2]), r3 = unpk(acc[i][3]);
            *(float4*)cp       = make_float4(r0.x, r0.y, r1.x, r1.y);
            *(float4*)(cp + 4) = make_float4(r2.x, r2.y, r3.x, r3.y);
        }
    }
}

// act = silu(G) * U, written in place into G
__global__ void act_kernel() {
    size_t idx = (size_t)blockIdx.x * blockDim.x + threadIdx.x;
    if (idx >= (size_t)NPAIRS * INTER) return;
    float g = d_G[idx];
    float u = d_U[idx];
    float s = g / (1.f + expf(-g));
    d_G[idx] = s * u;
}

// out[t][h] = w[2t]*Y[2t][h] + w[2t+1]*Y[2t+1][h]
__global__ void combine_kernel(float* __restrict__ out) {
    int idx = blockIdx.x * blockDim.x + threadIdx.x;
    if (idx >= T_TOKENS * HIDDEN) return;
    int t = idx >> 11;            // / HIDDEN (2048)
    int h = idx & (HIDDEN - 1);
    float w0 = d_wgt[2 * t], w1 = d_wgt[2 * t + 1];
    out[idx] = w0 * d_Y[(size_t)(2 * t) * HIDDEN + h]
             + w1 * d_Y[(size_t)(2 * t + 1) * HIDDEN + h];
}

// ---------------- launch ----------------
extern "C" void kernel_launch(void* const* d_in, const int* in_sizes, int n_in,
                              void* d_out, int out_size) {
    const float* x  = (const float*)d_in[0];
    const float* wr = (const float*)d_in[1];
    const float* wg = (const float*)d_in[2];
    const float* wu = (const float*)d_in[3];
    const float* wd = (const float*)d_in[4];
    float* out = (float*)d_out;

    init_kernel<<<1, 32>>>();
    router_kernel<<<T_TOKENS / 8, 256>>>(x, wr);
    compact_kernel<<<NPAIRS / 256, 256>>>();

    // G = x @ Wg^T   (M=pairs grouped, N=INTER, K=HIDDEN)
    dim3 g1(INTER / BN, CAP / BM, NEXP);
    gemm_expert<<<g1, 256>>>(x, wg, INTER, HIDDEN, HIDDEN, 1, 0, 0);
    // U = x @ Wu^T
    gemm_expert<<<g1, 256>>>(x, wu, INTER, HIDDEN, HIDDEN, 1, 0, 1);

    // act = silu(G) * U (in place into G)
    size_t total = (size_t)NPAIRS * INTER;
    act_kernel<<<(unsigned)((total + 255) / 256), 256>>>();

    // Y = act @ Wd^T  (N=HIDDEN, K=INTER)
    dim3 g3(HIDDEN / BN, CAP / BM, NEXP);
    gemm_expert<<<g3, 256>>>(nullptr, wd, HIDDEN, INTER, INTER, 0, 1, 2);

    // combine
    combine_kernel<<<(T_TOKENS * HIDDEN) / 256, 256>>>(out);
}

// round 3
// speedup vs baseline: 2.8831x; 2.8831x over previous
#include <cuda_runtime.h>
#include <math.h>
#include <stdint.h>

// Problem constants
#define T_TOKENS 2048
#define HIDDEN   2048
#define INTER    5632
#define NEXP     8
#define TOPK     2
#define NPAIRS   (T_TOKENS * TOPK)   // 4096
#define CAP      2048

// ---------------- device scratch ----------------
__device__ int d_cnt[NEXP];
__device__ int d_list[NEXP * CAP];
__device__ int d_eid[NPAIRS];
__device__ float d_wgt[NPAIRS];

__device__ __align__(16) float d_G[(size_t)NPAIRS * INTER];   // gate, then act (in-place)
__device__ __align__(16) float d_U[(size_t)NPAIRS * INTER];   // up
__device__ __align__(16) float d_Y[(size_t)NPAIRS * HIDDEN];  // per-pair down output

// ---------------- small kernels ----------------
__global__ void init_kernel() {
    if (threadIdx.x < NEXP) d_cnt[threadIdx.x] = 0;
}

__global__ void router_kernel(const float* __restrict__ x, const float* __restrict__ wr) {
    int warp = threadIdx.x >> 5;
    int lane = threadIdx.x & 31;
    int t = blockIdx.x * 8 + warp;
    if (t >= T_TOKENS) return;

    float acc[NEXP];
#pragma unroll
    for (int e = 0; e < NEXP; e++) acc[e] = 0.f;
    const float* xr = x + (size_t)t * HIDDEN;
    for (int j = lane; j < HIDDEN; j += 32) {
        float xv = xr[j];
#pragma unroll
        for (int e = 0; e < NEXP; e++) acc[e] += xv * wr[e * HIDDEN + j];
    }
#pragma unroll
    for (int e = 0; e < NEXP; e++) {
#pragma unroll
        for (int off = 16; off; off >>= 1)
            acc[e] += __shfl_xor_sync(0xffffffffu, acc[e], off);
    }
    if (lane == 0) {
        int e0 = 0;
#pragma unroll
        for (int e = 1; e < NEXP; e++) if (acc[e] > acc[e0]) e0 = e;
        int e1 = -1;
#pragma unroll
        for (int e = 0; e < NEXP; e++) {
            if (e == e0) continue;
            if (e1 < 0 || acc[e] > acc[e1]) e1 = e;
        }
        float v0 = acc[e0], v1 = acc[e1];
        float w1 = 1.f / (1.f + expf(v0 - v1));
        float w0 = 1.f - w1;
        d_eid[2 * t] = e0;  d_eid[2 * t + 1] = e1;
        d_wgt[2 * t] = w0;  d_wgt[2 * t + 1] = w1;
    }
}

__global__ void compact_kernel() {
    int p = blockIdx.x * blockDim.x + threadIdx.x;
    if (p >= NPAIRS) return;
    int e = d_eid[p];
    int pos = atomicAdd(&d_cnt[e], 1);
    d_list[e * CAP + pos] = p;
}

// ---------------- mma helpers (base-target tf32 tensor path) ----------------
__device__ __forceinline__ uint32_t tf32r(float x) {
    uint32_t r;
    asm("cvt.rna.tf32.f32 %0, %1;" : "=r"(r) : "f"(x));
    return r;
}
__device__ __forceinline__ void mma_tf32(float* c, const uint32_t* a, const uint32_t* b) {
    asm volatile("mma.sync.aligned.m16n8k8.row.col.f32.tf32.tf32.f32 "
                 "{%0,%1,%2,%3}, {%4,%5,%6,%7}, {%8,%9}, {%0,%1,%2,%3};"
                 : "+f"(c[0]), "+f"(c[1]), "+f"(c[2]), "+f"(c[3])
                 : "r"(a[0]), "r"(a[1]), "r"(a[2]), "r"(a[3]),
                   "r"(b[0]), "r"(b[1]));
}

// ---------------- expert-grouped tf32 tensor GEMM ----------------
// C[pid][n] = sum_k A[pid>>shift][k] * B_e[n][k]
// Tile: BM=BN=128, BK=32. 256 threads, 8 warps in 2(m) x 4(n), warp tile 64x32.
#define BK 32
#define SMS 36          // padded smem row stride (floats)

__global__ __launch_bounds__(256, 2)
void gemm_tc(const float* __restrict__ Aext, const float* __restrict__ Ball,
             int N, int K, int lda, int shift, int asel, int csel)
{
    int e = blockIdx.z;
    int n_e = d_cnt[e];
    int mbase = blockIdx.y * 128;
    if (mbase >= n_e) return;
    int nbase = blockIdx.x * 128;

    const float* A = asel ? d_G : Aext;
    float* C = (csel == 0) ? d_G : (csel == 1) ? d_U : d_Y;
    const float* B = Ball + (size_t)e * N * K;

    extern __shared__ float sm[];
    float* sA = sm;                        // [2][128][SMS]
    float* sB = sm + 2 * 128 * SMS;        // [2][128][SMS]
    int*   s_pid = (int*)(sB + 2 * 128 * SMS);   // [128]

    int tid = threadIdx.x;
    int lane = tid & 31;
    int wid = tid >> 5;
    int wm = wid & 1;          // 0..1  (64 rows each)
    int wn = wid >> 1;         // 0..3  (32 cols each)

    if (tid < 128) {
        int lp = mbase + tid;
        s_pid[tid] = d_list[e * CAP + (lp < n_e ? lp : mbase)];
    }
    __syncthreads();

    // ---- loader mapping: 4 chunks/thread, chunk = (row, 4 floats of k) ----
    const float* aP[4];
    const float* bP[4];
    int so[4];
#pragma unroll
    for (int i = 0; i < 4; i++) {
        int idx = tid + i * 256;
        int row = idx >> 3;
        int c4  = (idx & 7) * 4;
        aP[i] = A + (size_t)(s_pid[row] >> shift) * lda + c4;
        bP[i] = B + (size_t)(nbase + row) * K + c4;
        so[i] = row * SMS + c4;
    }

    float acc[4][4][4];
#pragma unroll
    for (int mt = 0; mt < 4; mt++)
#pragma unroll
        for (int nt = 0; nt < 4; nt++)
#pragma unroll
            for (int q = 0; q < 4; q++) acc[mt][nt][q] = 0.f;

    int KT = K / BK;

    // prologue: stage kb=0
    {
        float4 ra[4], rb[4];
#pragma unroll
        for (int i = 0; i < 4; i++) { ra[i] = *(const float4*)aP[i]; rb[i] = *(const float4*)bP[i]; }
#pragma unroll
        for (int i = 0; i < 4; i++) {
            uint4 ca = make_uint4(tf32r(ra[i].x), tf32r(ra[i].y), tf32r(ra[i].z), tf32r(ra[i].w));
            uint4 cb = make_uint4(tf32r(rb[i].x), tf32r(rb[i].y), tf32r(rb[i].z), tf32r(rb[i].w));
            *(uint4*)(sA + so[i]) = ca;
            *(uint4*)(sB + so[i]) = cb;
        }
    }
    __syncthreads();

    int arow = wm * 64 + (lane >> 2);
    int brow = wn * 32 + (lane >> 2);
    int kcol = lane & 3;

    for (int kb = 0; kb < KT; kb++) {
        int cur = kb & 1;
        float4 ra[4], rb[4];
        if (kb + 1 < KT) {
            int koff = (kb + 1) * BK;
#pragma unroll
            for (int i = 0; i < 4; i++) {
                ra[i] = *(const float4*)(aP[i] + koff);
                rb[i] = *(const float4*)(bP[i] + koff);
            }
        }

        const float* cA = sA + cur * 128 * SMS;
        const float* cB = sB + cur * 128 * SMS;
#pragma unroll
        for (int ks = 0; ks < 4; ks++) {
            int kc = ks * 8 + kcol;
            uint32_t af[4][4], bf[4][2];
#pragma unroll
            for (int mt = 0; mt < 4; mt++) {
                const float* p = cA + (arow + mt * 16) * SMS + kc;
                af[mt][0] = __float_as_uint(p[0]);
                af[mt][1] = __float_as_uint(p[8 * SMS]);
                af[mt][2] = __float_as_uint(p[4]);
                af[mt][3] = __float_as_uint(p[8 * SMS + 4]);
            }
#pragma unroll
            for (int nt = 0; nt < 4; nt++) {
                const float* p = cB + (brow + nt * 8) * SMS + kc;
                bf[nt][0] = __float_as_uint(p[0]);
                bf[nt][1] = __float_as_uint(p[4]);
            }
#pragma unroll
            for (int mt = 0; mt < 4; mt++)
#pragma unroll
                for (int nt = 0; nt < 4; nt++)
                    mma_tf32(acc[mt][nt], af[mt], bf[nt]);
        }

        if (kb + 1 < KT) {
            float* nA = sA + (cur ^ 1) * 128 * SMS;
            float* nB = sB + (cur ^ 1) * 128 * SMS;
#pragma unroll
            for (int i = 0; i < 4; i++) {
                uint4 ca = make_uint4(tf32r(ra[i].x), tf32r(ra[i].y), tf32r(ra[i].z), tf32r(ra[i].w));
                uint4 cb = make_uint4(tf32r(rb[i].x), tf32r(rb[i].y), tf32r(rb[i].z), tf32r(rb[i].w));
                *(uint4*)(nA + so[i]) = ca;
                *(uint4*)(nB + so[i]) = cb;
            }
            __syncthreads();
        }
    }

    // ---- epilogue: scatter accum rows via pid list ----
    int gid = lane >> 2;      // 0..7
    int tig = lane & 3;       // 0..3
#pragma unroll
    for (int mt = 0; mt < 4; mt++) {
        int mrow0 = wm * 64 + mt * 16 + gid;
        int mrow1 = mrow0 + 8;
        bool v0 = (mbase + mrow0) < n_e;
        bool v1 = (mbase + mrow1) < n_e;
        float* c0 = v0 ? (C + (size_t)s_pid[mrow0] * N + nbase + wn * 32 + tig * 2) : (float*)0;
        float* c1 = v1 ? (C + (size_t)s_pid[mrow1] * N + nbase + wn * 32 + tig * 2) : (float*)0;
#pragma unroll
        for (int nt = 0; nt < 4; nt++) {
            if (v0) *(float2*)(c0 + nt * 8) = make_float2(acc[mt][nt][0], acc[mt][nt][1]);
            if (v1) *(float2*)(c1 + nt * 8) = make_float2(acc[mt][nt][2], acc[mt][nt][3]);
        }
    }
}

#define DYN_BYTES (2 * 128 * SMS * 4 * 2 + 128 * 4 + 16)

// ---------------- elementwise ----------------
__global__ void act_kernel() {
    size_t i = (size_t)blockIdx.x * blockDim.x + threadIdx.x;
    if (i >= (size_t)NPAIRS * INTER / 4) return;
    float4 g = ((const float4*)d_G)[i];
    float4 u = ((const float4*)d_U)[i];
    float4 o;
    o.x = g.x / (1.f + expf(-g.x)) * u.x;
    o.y = g.y / (1.f + expf(-g.y)) * u.y;
    o.z = g.z / (1.f + expf(-g.z)) * u.z;
    o.w = g.w / (1.f + expf(-g.w)) * u.w;
    ((float4*)d_G)[i] = o;
}

__global__ void combine_kernel(float* __restrict__ out) {
    int idx = blockIdx.x * blockDim.x + threadIdx.x;
    if (idx >= T_TOKENS * HIDDEN / 4) return;
    int t = idx / (HIDDEN / 4);
    int h4 = idx % (HIDDEN / 4);
    float w0 = d_wgt[2 * t], w1 = d_wgt[2 * t + 1];
    float4 a = ((const float4*)d_Y)[(size_t)(2 * t) * (HIDDEN / 4) + h4];
    float4 b = ((const float4*)d_Y)[(size_t)(2 * t + 1) * (HIDDEN / 4) + h4];
    float4 o;
    o.x = w0 * a.x + w1 * b.x;
    o.y = w0 * a.y + w1 * b.y;
    o.z = w0 * a.z + w1 * b.z;
    o.w = w0 * a.w + w1 * b.w;
    ((float4*)out)[idx] = o;
}

// ---------------- launch ----------------
extern "C" void kernel_launch(void* const* d_in, const int* in_sizes, int n_in,
                              void* d_out, int out_size) {
    const float* x  = (const float*)d_in[0];
    const float* wr = (const float*)d_in[1];
    const float* wg = (const float*)d_in[2];
    const float* wu = (const float*)d_in[3];
    const float* wd = (const float*)d_in[4];
    float* out = (float*)d_out;

    cudaFuncSetAttribute(gemm_tc, cudaFuncAttributeMaxDynamicSharedMemorySize, DYN_BYTES);

    init_kernel<<<1, 32>>>();
    router_kernel<<<T_TOKENS / 8, 256>>>(x, wr);
    compact_kernel<<<NPAIRS / 256, 256>>>();

    // G = x @ Wg^T   (N=INTER, K=HIDDEN)
    dim3 g1(INTER / 128, CAP / 128, NEXP);
    gemm_tc<<<g1, 256, DYN_BYTES>>>(x, wg, INTER, HIDDEN, HIDDEN, 1, 0, 0);
    // U = x @ Wu^T
    gemm_tc<<<g1, 256, DYN_BYTES>>>(x, wu, INTER, HIDDEN, HIDDEN, 1, 0, 1);

    // act = silu(G) * U
    size_t total4 = (size_t)NPAIRS * INTER / 4;
    act_kernel<<<(unsigned)((total4 + 255) / 256), 256>>>();

    // Y = act @ Wd^T  (N=HIDDEN, K=INTER)
    dim3 g3(HIDDEN / 128, CAP / 128, NEXP);
    gemm_tc<<<g3, 256, DYN_BYTES>>>(nullptr, wd, HIDDEN, INTER, INTER, 0, 1, 2);

    combine_kernel<<<(T_TOKENS * HIDDEN / 4) / 256, 256>>>(out);
}

// round 4
// speedup vs baseline: 2.9671x; 1.0291x over previous
#include <cuda_runtime.h>
#include <math.h>
#include <stdint.h>

// Problem constants
#define T_TOKENS 2048
#define HIDDEN   2048
#define INTER    5632
#define NEXP     8
#define TOPK     2
#define NPAIRS   (T_TOKENS * TOPK)   // 4096
#define CAP      2048

// ---------------- device scratch ----------------
__device__ int d_cnt[NEXP];
__device__ int d_list[NEXP * CAP];
__device__ int d_eid[NPAIRS];
__device__ float d_wgt[NPAIRS];

__device__ __align__(16) float d_G[(size_t)NPAIRS * INTER];   // gate, then act (in-place)
__device__ __align__(16) float d_U[(size_t)NPAIRS * INTER];   // up
__device__ __align__(16) float d_Y[(size_t)NPAIRS * HIDDEN];  // per-pair down output

// ---------------- small kernels ----------------
__global__ void init_kernel() {
    if (threadIdx.x < NEXP) d_cnt[threadIdx.x] = 0;
}

__global__ void router_kernel(const float* __restrict__ x, const float* __restrict__ wr) {
    int warp = threadIdx.x >> 5;
    int lane = threadIdx.x & 31;
    int t = blockIdx.x * 8 + warp;
    if (t >= T_TOKENS) return;

    float acc[NEXP];
#pragma unroll
    for (int e = 0; e < NEXP; e++) acc[e] = 0.f;
    const float* xr = x + (size_t)t * HIDDEN;
    for (int j = lane; j < HIDDEN; j += 32) {
        float xv = xr[j];
#pragma unroll
        for (int e = 0; e < NEXP; e++) acc[e] += xv * wr[e * HIDDEN + j];
    }
#pragma unroll
    for (int e = 0; e < NEXP; e++) {
#pragma unroll
        for (int off = 16; off; off >>= 1)
            acc[e] += __shfl_xor_sync(0xffffffffu, acc[e], off);
    }
    if (lane == 0) {
        int e0 = 0;
#pragma unroll
        for (int e = 1; e < NEXP; e++) if (acc[e] > acc[e0]) e0 = e;
        int e1 = -1;
#pragma unroll
        for (int e = 0; e < NEXP; e++) {
            if (e == e0) continue;
            if (e1 < 0 || acc[e] > acc[e1]) e1 = e;
        }
        float v0 = acc[e0], v1 = acc[e1];
        float w1 = 1.f / (1.f + expf(v0 - v1));
        float w0 = 1.f - w1;
        d_eid[2 * t] = e0;  d_eid[2 * t + 1] = e1;
        d_wgt[2 * t] = w0;  d_wgt[2 * t + 1] = w1;
    }
}

__global__ void compact_kernel() {
    int p = blockIdx.x * blockDim.x + threadIdx.x;
    if (p >= NPAIRS) return;
    int e = d_eid[p];
    int pos = atomicAdd(&d_cnt[e], 1);
    d_list[e * CAP + pos] = p;
}

// ---------------- helpers ----------------
__device__ __forceinline__ uint32_t smem_u32(const void* p) {
    uint32_t a;
    asm("{ .reg .u64 t; cvta.to.shared.u64 t, %1; cvt.u32.u64 %0, t; }" : "=r"(a) : "l"(p));
    return a;
}
__device__ __forceinline__ uint32_t tf32r(float x) {
    uint32_t r;
    asm("cvt.rna.tf32.f32 %0, %1;" : "=r"(r) : "f"(x));
    return r;
}
__device__ __forceinline__ void mma_tf32(float* c, const uint32_t* a, const uint32_t* b) {
    asm volatile("mma.sync.aligned.m16n8k8.row.col.f32.tf32.tf32.f32 "
                 "{%0,%1,%2,%3}, {%4,%5,%6,%7}, {%8,%9}, {%0,%1,%2,%3};"
                 : "+f"(c[0]), "+f"(c[1]), "+f"(c[2]), "+f"(c[3])
                 : "r"(a[0]), "r"(a[1]), "r"(a[2]), "r"(a[3]),
                   "r"(b[0]), "r"(b[1]));
}
__device__ __forceinline__ void cp16(uint32_t smem_dst, const void* gptr) {
    asm volatile("cp.async.cg.shared.global [%0], [%1], 16;" :: "r"(smem_dst), "l"(gptr));
}

// ---------------- expert-grouped tf32 tensor GEMM, cp.async 3-stage ----------------
// C[pid][n] = sum_k A[pid>>shift][k] * B_e[n][k]
// Tile: BM=BN=128, BK=32. 256 threads, 8 warps in 2(m) x 4(n), warp tile 64x32.
#define BK 32
#define SMS 36                      // padded smem row stride (floats)
#define STAGE_F (256 * SMS)         // floats per stage (128 A rows + 128 B rows)
#define NSTAGE 3

__global__ __launch_bounds__(256, 2)
void gemm_tc(const float* __restrict__ Aext, const float* __restrict__ Ball,
             int N, int K, int lda, int shift, int asel, int csel)
{
    int e = blockIdx.z;
    int n_e = d_cnt[e];
    int mbase = blockIdx.y * 128;
    if (mbase >= n_e) return;
    int nbase = blockIdx.x * 128;

    const float* A = asel ? d_G : Aext;
    float* C = (csel == 0) ? d_G : (csel == 1) ? d_U : d_Y;
    const float* B = Ball + (size_t)e * N * K;

    extern __shared__ float sm[];
    int* s_pid = (int*)(sm + NSTAGE * STAGE_F);
    uint32_t smbase = smem_u32(sm);

    int tid = threadIdx.x;
    int lane = tid & 31;
    int wid = tid >> 5;
    int wm = wid & 1;          // 0..1  (64 rows each)
    int wn = wid >> 1;         // 0..3  (32 cols each)

    if (tid < 128) {
        int lp = mbase + tid;
        s_pid[tid] = d_list[e * CAP + (lp < n_e ? lp : mbase)];
    }
    __syncthreads();

    // loader mapping: 4 chunks/thread per operand; chunk = (row, 16B of k)
    const char* aG[4];
    const char* bG[4];
    uint32_t aS[4], bS[4];     // smem byte offsets within a stage
#pragma unroll
    for (int i = 0; i < 4; i++) {
        int idx = tid + i * 256;
        int row = idx >> 3;
        int c4  = (idx & 7) * 4;
        aG[i] = (const char*)(A + (size_t)(s_pid[row] >> shift) * lda + c4);
        bG[i] = (const char*)(B + (size_t)(nbase + row) * K + c4);
        aS[i] = (uint32_t)((row * SMS + c4) * 4);
        bS[i] = (uint32_t)((128 * SMS + row * SMS + c4) * 4);
    }

    int KT = K / BK;

    // issue one stage's cp.asyncs (stage st, k-block kb)
    auto issue = [&](int st, int kb) {
        uint32_t sb = smbase + (uint32_t)(st * STAGE_F * 4);
        size_t go = (size_t)kb * BK * 4;
#pragma unroll
        for (int i = 0; i < 4; i++) cp16(sb + aS[i], aG[i] + go);
#pragma unroll
        for (int i = 0; i < 4; i++) cp16(sb + bS[i], bG[i] + go);
        asm volatile("cp.async.commit_group;" ::: "memory");
    };

    // prologue: stages 0,1
    issue(0, 0);
    issue(1, 1);

    float acc[4][4][4];
#pragma unroll
    for (int mt = 0; mt < 4; mt++)
#pragma unroll
        for (int nt = 0; nt < 4; nt++)
#pragma unroll
            for (int q = 0; q < 4; q++) acc[mt][nt][q] = 0.f;

    int arow = wm * 64 + (lane >> 2);
    int brow = wn * 32 + (lane >> 2);
    int kcol = lane & 3;

    for (int kb = 0; kb < KT; kb++) {
        int st = kb % NSTAGE;
        if (kb + 2 < KT) {
            __syncthreads();                       // WAR: stage (kb+2)%3 fully consumed
            issue((kb + 2) % NSTAGE, kb + 2);
            asm volatile("cp.async.wait_group 2;" ::: "memory");
        } else if (kb + 1 < KT) {
            asm volatile("cp.async.wait_group 1;" ::: "memory");
        } else {
            asm volatile("cp.async.wait_group 0;" ::: "memory");
        }
        __syncthreads();                           // stage kb visible to all

        const float* cA = sm + st * STAGE_F;
        const float* cB = cA + 128 * SMS;
#pragma unroll
        for (int ks = 0; ks < 4; ks++) {
            int kc = ks * 8 + kcol;
            uint32_t af[4][4], bf[4][2];
#pragma unroll
            for (int mt = 0; mt < 4; mt++) {
                const float* p = cA + (arow + mt * 16) * SMS + kc;
                af[mt][0] = tf32r(p[0]);
                af[mt][1] = tf32r(p[8 * SMS]);
                af[mt][2] = tf32r(p[4]);
                af[mt][3] = tf32r(p[8 * SMS + 4]);
            }
#pragma unroll
            for (int nt = 0; nt < 4; nt++) {
                const float* p = cB + (brow + nt * 8) * SMS + kc;
                bf[nt][0] = tf32r(p[0]);
                bf[nt][1] = tf32r(p[4]);
            }
#pragma unroll
            for (int mt = 0; mt < 4; mt++)
#pragma unroll
                for (int nt = 0; nt < 4; nt++)
                    mma_tf32(acc[mt][nt], af[mt], bf[nt]);
        }
    }

    // ---- epilogue: scatter accum rows via pid list ----
    int gid = lane >> 2;      // 0..7
    int tig = lane & 3;       // 0..3
#pragma unroll
    for (int mt = 0; mt < 4; mt++) {
        int mrow0 = wm * 64 + mt * 16 + gid;
        int mrow1 = mrow0 + 8;
        bool v0 = (mbase + mrow0) < n_e;
        bool v1 = (mbase + mrow1) < n_e;
        float* c0 = v0 ? (C + (size_t)s_pid[mrow0] * N + nbase + wn * 32 + tig * 2) : (float*)0;
        float* c1 = v1 ? (C + (size_t)s_pid[mrow1] * N + nbase + wn * 32 + tig * 2) : (float*)0;
#pragma unroll
        for (int nt = 0; nt < 4; nt++) {
            if (v0) *(float2*)(c0 + nt * 8) = make_float2(acc[mt][nt][0], acc[mt][nt][1]);
            if (v1) *(float2*)(c1 + nt * 8) = make_float2(acc[mt][nt][2], acc[mt][nt][3]);
        }
    }
}

#define DYN_BYTES (NSTAGE * STAGE_F * 4 + 128 * 4 + 16)

// ---------------- elementwise ----------------
__global__ void act_kernel() {
    size_t i = (size_t)blockIdx.x * blockDim.x + threadIdx.x;
    if (i >= (size_t)NPAIRS * INTER / 4) return;
    float4 g = ((const float4*)d_G)[i];
    float4 u = ((const float4*)d_U)[i];
    float4 o;
    o.x = g.x / (1.f + expf(-g.x)) * u.x;
    o.y = g.y / (1.f + expf(-g.y)) * u.y;
    o.z = g.z / (1.f + expf(-g.z)) * u.z;
    o.w = g.w / (1.f + expf(-g.w)) * u.w;
    ((float4*)d_G)[i] = o;
}

__global__ void combine_kernel(float* __restrict__ out) {
    int idx = blockIdx.x * blockDim.x + threadIdx.x;
    if (idx >= T_TOKENS * HIDDEN / 4) return;
    int t = idx / (HIDDEN / 4);
    int h4 = idx % (HIDDEN / 4);
    float w0 = d_wgt[2 * t], w1 = d_wgt[2 * t + 1];
    float4 a = ((const float4*)d_Y)[(size_t)(2 * t) * (HIDDEN / 4) + h4];
    float4 b = ((const float4*)d_Y)[(size_t)(2 * t + 1) * (HIDDEN / 4) + h4];
    float4 o;
    o.x = w0 * a.x + w1 * b.x;
    o.y = w0 * a.y + w1 * b.y;
    o.z = w0 * a.z + w1 * b.z;
    o.w = w0 * a.w + w1 * b.w;
    ((float4*)out)[idx] = o;
}

// ---------------- launch ----------------
extern "C" void kernel_launch(void* const* d_in, const int* in_sizes, int n_in,
                              void* d_out, int out_size) {
    const float* x  = (const float*)d_in[0];
    const float* wr = (const float*)d_in[1];
    const float* wg = (const float*)d_in[2];
    const float* wu = (const float*)d_in[3];
    const float* wd = (const float*)d_in[4];
    float* out = (float*)d_out;

    cudaFuncSetAttribute(gemm_tc, cudaFuncAttributeMaxDynamicSharedMemorySize, DYN_BYTES);

    init_kernel<<<1, 32>>>();
    router_kernel<<<T_TOKENS / 8, 256>>>(x, wr);
    compact_kernel<<<NPAIRS / 256, 256>>>();

    // G = x @ Wg^T   (N=INTER, K=HIDDEN)
    dim3 g1(INTER / 128, CAP / 128, NEXP);
    gemm_tc<<<g1, 256, DYN_BYTES>>>(x, wg, INTER, HIDDEN, HIDDEN, 1, 0, 0);
    // U = x @ Wu^T
    gemm_tc<<<g1, 256, DYN_BYTES>>>(x, wu, INTER, HIDDEN, HIDDEN, 1, 0, 1);

    // act = silu(G) * U
    size_t total4 = (size_t)NPAIRS * INTER / 4;
    act_kernel<<<(unsigned)((total4 + 255) / 256), 256>>>();

    // Y = act @ Wd^T  (N=HIDDEN, K=INTER)
    dim3 g3(HIDDEN / 128, CAP / 128, NEXP);
    gemm_tc<<<g3, 256, DYN_BYTES>>>(nullptr, wd, HIDDEN, INTER, INTER, 0, 1, 2);

    combine_kernel<<<(T_TOKENS * HIDDEN / 4) / 256, 256>>>(out);
}

// round 5
// speedup vs baseline: 3.0507x; 1.0282x over previous
#include <cuda_runtime.h>
#include <math.h>
#include <stdint.h>

// Problem constants
#define T_TOKENS 2048
#define HIDDEN   2048
#define INTER    5632
#define NEXP     8
#define TOPK     2
#define NPAIRS   (T_TOKENS * TOPK)   // 4096
#define CAP      2048

// ---------------- device scratch ----------------
__device__ int d_cnt[NEXP];
__device__ int d_list[NEXP * CAP];
__device__ int d_eid[NPAIRS];
__device__ float d_wgt[NPAIRS];

__device__ __align__(16) float d_G[(size_t)NPAIRS * INTER];   // gate, then act (in-place)
__device__ __align__(16) float d_U[(size_t)NPAIRS * INTER];   // up
__device__ __align__(16) float d_Y[(size_t)NPAIRS * HIDDEN];  // per-pair down output

// ---------------- small kernels ----------------
__global__ void init_kernel() {
    if (threadIdx.x < NEXP) d_cnt[threadIdx.x] = 0;
}

__global__ void router_kernel(const float* __restrict__ x, const float* __restrict__ wr) {
    int warp = threadIdx.x >> 5;
    int lane = threadIdx.x & 31;
    int t = blockIdx.x * 8 + warp;
    if (t >= T_TOKENS) return;

    float acc[NEXP];
#pragma unroll
    for (int e = 0; e < NEXP; e++) acc[e] = 0.f;
    const float* xr = x + (size_t)t * HIDDEN;
    for (int j = lane; j < HIDDEN; j += 32) {
        float xv = xr[j];
#pragma unroll
        for (int e = 0; e < NEXP; e++) acc[e] += xv * wr[e * HIDDEN + j];
    }
#pragma unroll
    for (int e = 0; e < NEXP; e++) {
#pragma unroll
        for (int off = 16; off; off >>= 1)
            acc[e] += __shfl_xor_sync(0xffffffffu, acc[e], off);
    }
    if (lane == 0) {
        int e0 = 0;
#pragma unroll
        for (int e = 1; e < NEXP; e++) if (acc[e] > acc[e0]) e0 = e;
        int e1 = -1;
#pragma unroll
        for (int e = 0; e < NEXP; e++) {
            if (e == e0) continue;
            if (e1 < 0 || acc[e] > acc[e1]) e1 = e;
        }
        float v0 = acc[e0], v1 = acc[e1];
        float w1 = 1.f / (1.f + expf(v0 - v1));
        float w0 = 1.f - w1;
        d_eid[2 * t] = e0;  d_eid[2 * t + 1] = e1;
        d_wgt[2 * t] = w0;  d_wgt[2 * t + 1] = w1;
    }
}

__global__ void compact_kernel() {
    int p = blockIdx.x * blockDim.x + threadIdx.x;
    if (p >= NPAIRS) return;
    int e = d_eid[p];
    int pos = atomicAdd(&d_cnt[e], 1);
    d_list[e * CAP + pos] = p;
}

// ---------------- helpers ----------------
__device__ __forceinline__ uint32_t smem_u32(const void* p) {
    uint32_t a;
    asm("{ .reg .u64 t; cvta.to.shared.u64 t, %1; cvt.u32.u64 %0, t; }" : "=r"(a) : "l"(p));
    return a;
}
__device__ __forceinline__ uint32_t tf32r(float x) {
    uint32_t r;
    asm("cvt.rna.tf32.f32 %0, %1;" : "=r"(r) : "f"(x));
    return r;
}
__device__ __forceinline__ void mma_tf32(float* c, const uint32_t* a, const uint32_t* b) {
    asm volatile("mma.sync.aligned.m16n8k8.row.col.f32.tf32.tf32.f32 "
                 "{%0,%1,%2,%3}, {%4,%5,%6,%7}, {%8,%9}, {%0,%1,%2,%3};"
                 : "+f"(c[0]), "+f"(c[1]), "+f"(c[2]), "+f"(c[3])
                 : "r"(a[0]), "r"(a[1]), "r"(a[2]), "r"(a[3]),
                   "r"(b[0]), "r"(b[1]));
}
__device__ __forceinline__ void cp16(uint32_t smem_dst, const void* gptr) {
    asm volatile("cp.async.cg.shared.global [%0], [%1], 16;" :: "r"(smem_dst), "l"(gptr));
}

// ---------------- expert-grouped tf32 tensor GEMM ----------------
// C[pid][n] = sum_k A[pid>>shift][k] * B_e[n][k]
// Tile: BM=128, BN=256, BK=32. 256 threads, 8 warps in 2(m) x 4(n), warp tile 64x64.
#define BK 32
#define SMS 36                                 // padded smem row stride (floats)
#define STAGE_F ((128 + 256) * SMS)            // floats per stage: A(128) + B(256) rows
#define NSTAGE 3

__global__ __launch_bounds__(256, 1)
void gemm_tc(const float* __restrict__ Aext, const float* __restrict__ Ball,
             int N, int K, int lda, int shift, int asel, int csel)
{
    int e = blockIdx.z;
    int n_e = d_cnt[e];
    int mbase = blockIdx.y * 128;
    if (mbase >= n_e) return;
    int nbase = blockIdx.x * 256;

    const float* A = asel ? d_G : Aext;
    float* C = (csel == 0) ? d_G : (csel == 1) ? d_U : d_Y;
    const float* B = Ball + (size_t)e * N * K;

    extern __shared__ float sm[];
    int* s_pid = (int*)(sm + NSTAGE * STAGE_F);
    uint32_t smbase = smem_u32(sm);

    int tid = threadIdx.x;
    int lane = tid & 31;
    int wid = tid >> 5;
    int wm = wid & 1;          // 0..1  (64 rows each)
    int wn = wid >> 1;         // 0..3  (64 cols each)

    if (tid < 128) {
        int lp = mbase + tid;
        s_pid[tid] = d_list[e * CAP + (lp < n_e ? lp : mbase)];
    }
    __syncthreads();

    // loader mapping: A 4 chunks/thread, B 8 chunks/thread; chunk = (row, 16B of k)
    const char* aG[4];
    const char* bG[8];
    uint32_t aS[4], bS[8];
#pragma unroll
    for (int i = 0; i < 4; i++) {
        int idx = tid + i * 256;          // 0..1023
        int row = idx >> 3;
        int c4  = (idx & 7) * 4;
        aG[i] = (const char*)(A + (size_t)(s_pid[row] >> shift) * lda + c4);
        aS[i] = (uint32_t)((row * SMS + c4) * 4);
    }
#pragma unroll
    for (int i = 0; i < 8; i++) {
        int idx = tid + i * 256;          // 0..2047
        int row = idx >> 3;
        int c4  = (idx & 7) * 4;
        bG[i] = (const char*)(B + (size_t)(nbase + row) * K + c4);
        bS[i] = (uint32_t)((128 * SMS + row * SMS + c4) * 4);
    }

    int KT = K / BK;

    auto issue = [&](int st, int kb) {
        uint32_t sb = smbase + (uint32_t)(st * STAGE_F * 4);
        size_t go = (size_t)kb * BK * 4;
#pragma unroll
        for (int i = 0; i < 4; i++) cp16(sb + aS[i], aG[i] + go);
#pragma unroll
        for (int i = 0; i < 8; i++) cp16(sb + bS[i], bG[i] + go);
        asm volatile("cp.async.commit_group;" ::: "memory");
    };

    issue(0, 0);
    issue(1, 1);

    float acc[4][8][4];
#pragma unroll
    for (int mt = 0; mt < 4; mt++)
#pragma unroll
        for (int nt = 0; nt < 8; nt++)
#pragma unroll
            for (int q = 0; q < 4; q++) acc[mt][nt][q] = 0.f;

    int arow = wm * 64 + (lane >> 2);
    int brow = wn * 64 + (lane >> 2);
    int kcol = lane & 3;

    for (int kb = 0; kb < KT; kb++) {
        int st = kb % NSTAGE;
        if (kb + 2 < KT) {
            __syncthreads();                       // WAR: stage (kb+2)%3 fully consumed
            issue((kb + 2) % NSTAGE, kb + 2);
            asm volatile("cp.async.wait_group 2;" ::: "memory");
        } else if (kb + 1 < KT) {
            asm volatile("cp.async.wait_group 1;" ::: "memory");
        } else {
            asm volatile("cp.async.wait_group 0;" ::: "memory");
        }
        __syncthreads();                           // stage kb visible

        const float* cA = sm + st * STAGE_F;
        const float* cB = cA + 128 * SMS;
#pragma unroll
        for (int ks = 0; ks < 4; ks++) {
            int kc = ks * 8 + kcol;
            uint32_t af[4][4], bf[8][2];
#pragma unroll
            for (int mt = 0; mt < 4; mt++) {
                const float* p = cA + (arow + mt * 16) * SMS + kc;
                af[mt][0] = tf32r(p[0]);
                af[mt][1] = tf32r(p[8 * SMS]);
                af[mt][2] = tf32r(p[4]);
                af[mt][3] = tf32r(p[8 * SMS + 4]);
            }
#pragma unroll
            for (int nt = 0; nt < 8; nt++) {
                const float* p = cB + (brow + nt * 8) * SMS + kc;
                bf[nt][0] = tf32r(p[0]);
                bf[nt][1] = tf32r(p[4]);
            }
#pragma unroll
            for (int mt = 0; mt < 4; mt++)
#pragma unroll
                for (int nt = 0; nt < 8; nt++)
                    mma_tf32(acc[mt][nt], af[mt], bf[nt]);
        }
    }

    // ---- epilogue: scatter accum rows via pid list ----
    int gid = lane >> 2;      // 0..7
    int tig = lane & 3;       // 0..3
#pragma unroll
    for (int mt = 0; mt < 4; mt++) {
        int mrow0 = wm * 64 + mt * 16 + gid;
        int mrow1 = mrow0 + 8;
        bool v0 = (mbase + mrow0) < n_e;
        bool v1 = (mbase + mrow1) < n_e;
        float* c0 = v0 ? (C + (size_t)s_pid[mrow0] * N + nbase + wn * 64 + tig * 2) : (float*)0;
        float* c1 = v1 ? (C + (size_t)s_pid[mrow1] * N + nbase + wn * 64 + tig * 2) : (float*)0;
#pragma unroll
        for (int nt = 0; nt < 8; nt++) {
            if (v0) *(float2*)(c0 + nt * 8) = make_float2(acc[mt][nt][0], acc[mt][nt][1]);
            if (v1) *(float2*)(c1 + nt * 8) = make_float2(acc[mt][nt][2], acc[mt][nt][3]);
        }
    }
}

#define DYN_BYTES (NSTAGE * STAGE_F * 4 + 128 * 4 + 16)

// ---------------- elementwise ----------------
__global__ void act_kernel() {
    size_t i = (size_t)blockIdx.x * blockDim.x + threadIdx.x;
    if (i >= (size_t)NPAIRS * INTER / 4) return;
    float4 g = ((const float4*)d_G)[i];
    float4 u = ((const float4*)d_U)[i];
    float4 o;
    o.x = g.x / (1.f + expf(-g.x)) * u.x;
    o.y = g.y / (1.f + expf(-g.y)) * u.y;
    o.z = g.z / (1.f + expf(-g.z)) * u.z;
    o.w = g.w / (1.f + expf(-g.w)) * u.w;
    ((float4*)d_G)[i] = o;
}

__global__ void combine_kernel(float* __restrict__ out) {
    int idx = blockIdx.x * blockDim.x + threadIdx.x;
    if (idx >= T_TOKENS * HIDDEN / 4) return;
    int t = idx / (HIDDEN / 4);
    int h4 = idx % (HIDDEN / 4);
    float w0 = d_wgt[2 * t], w1 = d_wgt[2 * t + 1];
    float4 a = ((const float4*)d_Y)[(size_t)(2 * t) * (HIDDEN / 4) + h4];
    float4 b = ((const float4*)d_Y)[(size_t)(2 * t + 1) * (HIDDEN / 4) + h4];
    float4 o;
    o.x = w0 * a.x + w1 * b.x;
    o.y = w0 * a.y + w1 * b.y;
    o.z = w0 * a.z + w1 * b.z;
    o.w = w0 * a.w + w1 * b.w;
    ((float4*)out)[idx] = o;
}

// ---------------- launch ----------------
extern "C" void kernel_launch(void* const* d_in, const int* in_sizes, int n_in,
                              void* d_out, int out_size) {
    const float* x  = (const float*)d_in[0];
    const float* wr = (const float*)d_in[1];
    const float* wg = (const float*)d_in[2];
    const float* wu = (const float*)d_in[3];
    const float* wd = (const float*)d_in[4];
    float* out = (float*)d_out;

    cudaFuncSetAttribute(gemm_tc, cudaFuncAttributeMaxDynamicSharedMemorySize, DYN_BYTES);

    init_kernel<<<1, 32>>>();
    router_kernel<<<T_TOKENS / 8, 256>>>(x, wr);
    compact_kernel<<<NPAIRS / 256, 256>>>();

    // G = x @ Wg^T   (N=INTER, K=HIDDEN)
    dim3 g1(INTER / 256, CAP / 128, NEXP);
    gemm_tc<<<g1, 256, DYN_BYTES>>>(x, wg, INTER, HIDDEN, HIDDEN, 1, 0, 0);
    // U = x @ Wu^T
    gemm_tc<<<g1, 256, DYN_BYTES>>>(x, wu, INTER, HIDDEN, HIDDEN, 1, 0, 1);

    // act = silu(G) * U
    size_t total4 = (size_t)NPAIRS * INTER / 4;
    act_kernel<<<(unsigned)((total4 + 255) / 256), 256>>>();

    // Y = act @ Wd^T  (N=HIDDEN, K=INTER)
    dim3 g3(HIDDEN / 256, CAP / 128, NEXP);
    gemm_tc<<<g3, 256, DYN_BYTES>>>(nullptr, wd, HIDDEN, INTER, INTER, 0, 1, 2);

    combine_kernel<<<(T_TOKENS * HIDDEN / 4) / 256, 256>>>(out);
}